// round 14
// baseline (speedup 1.0000x reference)
#include <cuda_runtime.h>
#include <math.h>
#include <stdint.h>

constexpr int cB = 4;
constexpr int cS = 4096;
constexpr int cN = 256;
constexpr int cD = 1024;
constexpr int cG = 16;
constexpr int cC = 64;
constexpr long SMALL_MN = (long)cB * cN * cD;

// ---------------------------------------------------------------------------
// Static device scratch
// ---------------------------------------------------------------------------
__device__ float g_nk [cB * cS * cD];
__device__ float g_nv [cB * cS * cD];
__device__ float g_k  [cB * cS * cD];
__device__ float g_v  [cB * cS * cD];
__device__ float g_nq [cB * cN * cD];
__device__ float g_q  [cB * cN * cD];
__device__ float g_ao [cB * cN * cD];
__device__ float g_p1 [cB * cN * cD];
__device__ float g_p2 [cB * cN * cD];
__device__ float g_t  [cB * cN * cD];
__device__ float g_h  [cB * cN * cD];
__device__ float g_part[2 * cB * cN * cD];
__device__ float g_cwq[cD * cD], g_cwk[cD * cD], g_cwv[cD * cD];
__device__ float g_cwp[cD * cD], g_cw1[cD * cD], g_cw2[cD * cD];
__device__ float g_cwr[cN * cN];
__device__ int   g_mask[cB * cS];
__device__ int   g_flag[1];

// ---------------------------------------------------------------------------
// tf32 helpers
// ---------------------------------------------------------------------------
__device__ __forceinline__ uint32_t f2tf(float f) {
    uint32_t u;
    asm("cvt.rna.tf32.f32 %0, %1;" : "=r"(u) : "f"(f));
    return u;
}
__device__ __forceinline__ float roundtf(float f) { return __uint_as_float(f2tf(f)); }

__device__ __forceinline__ void mma8(float* c, const uint32_t* a, const uint32_t* b) {
    asm volatile(
        "mma.sync.aligned.m16n8k8.row.col.f32.tf32.tf32.f32 "
        "{%0,%1,%2,%3}, {%4,%5,%6,%7}, {%8,%9}, {%0,%1,%2,%3};"
        : "+f"(c[0]), "+f"(c[1]), "+f"(c[2]), "+f"(c[3])
        : "r"(a[0]), "r"(a[1]), "r"(a[2]), "r"(a[3]), "r"(b[0]), "r"(b[1]));
}

#define CP16(smem_u32, gptr) \
    asm volatile("cp.async.ca.shared.global [%0], [%1], 16;" :: "r"(smem_u32), "l"(gptr))
#define CP_COMMIT() asm volatile("cp.async.commit_group;")
#define CP_WAIT2()  asm volatile("cp.async.wait_group 2;")

__device__ __forceinline__ uint32_t smem_addr_u32(const void* p) {
    return (uint32_t)__cvta_generic_to_shared(p);
}

__device__ __forceinline__ float gelu1(float v) {
    return 0.5f * v * (1.f + erff(v * 0.70710678118654752f));
}

__device__ __forceinline__ float warp_sum(float s) {
#pragma unroll
    for (int o = 16; o; o >>= 1) s += __shfl_xor_sync(0xffffffffu, s, o);
    return s;
}
__device__ __forceinline__ float warp_max(float s) {
#pragma unroll
    for (int o = 16; o; o >>= 1) s = fmaxf(s, __shfl_xor_sync(0xffffffffu, s, o));
    return s;
}

// ---------------------------------------------------------------------------
// Mask handling
// ---------------------------------------------------------------------------
__global__ void detect_mask_kernel(const unsigned char* __restrict__ p, int* flag) {
    __shared__ int red[256];
    int t = threadIdx.x;
    int cnt = 0;
    for (int i = t; i < cB * cS; i += 256)
        if ((i & 3) != 0 && p[i] != 0) cnt++;
    red[t] = cnt;
    __syncthreads();
    for (int s = 128; s > 0; s >>= 1) {
        if (t < s) red[t] += red[t + s];
        __syncthreads();
    }
    if (t == 0) flag[0] = red[0];
}

__global__ void expand_mask_kernel(const void* __restrict__ p, const int* __restrict__ flag,
                                   int* __restrict__ mout) {
    int i = blockIdx.x * 256 + threadIdx.x;
    if (i >= cB * cS) return;
    int isbyte = flag[0] > 0;
    int v = isbyte ? (int)((const unsigned char*)p)[i] : ((const int*)p)[i];
    mout[i] = (v != 0) ? 1 : 0;
}

// ---------------------------------------------------------------------------
// One-shot weight conversion, float4
// ---------------------------------------------------------------------------
__device__ __forceinline__ float4 round4(float4 v) {
    v.x = roundtf(v.x); v.y = roundtf(v.y); v.z = roundtf(v.z); v.w = roundtf(v.w);
    return v;
}

__global__ void cvt_all_kernel(
    const float* __restrict__ wq, const float* __restrict__ wk, const float* __restrict__ wv,
    const float* __restrict__ wp, const float* __restrict__ w1, const float* __restrict__ w2,
    const float* __restrict__ wr,
    float* __restrict__ dq, float* __restrict__ dk, float* __restrict__ dv,
    float* __restrict__ dp, float* __restrict__ d1, float* __restrict__ d2,
    float* __restrict__ dr) {
    int i = blockIdx.x * 256 + threadIdx.x;
    if (i < cD * cD / 4) {
        ((float4*)dq)[i] = round4(((const float4*)wq)[i]);
        ((float4*)dk)[i] = round4(((const float4*)wk)[i]);
        ((float4*)dv)[i] = round4(((const float4*)wv)[i]);
        ((float4*)dp)[i] = round4(((const float4*)wp)[i]);
        ((float4*)d1)[i] = round4(((const float4*)w1)[i]);
        ((float4*)d2)[i] = round4(((const float4*)w2)[i]);
    }
    if (i < cN * cN / 4) ((float4*)dr)[i] = round4(((const float4*)wr)[i]);
}

// ---------------------------------------------------------------------------
// LayerNorm, register-resident.
// ---------------------------------------------------------------------------
__global__ void __launch_bounds__(256) ln_kernel(
    const float* __restrict__ x, const float* __restrict__ add, int addmode,
    const float* __restrict__ w, const float* __restrict__ bias,
    float* __restrict__ out) {
    __shared__ float wred[8];
    int r = blockIdx.x, t = threadIdx.x;
    float4 v = ((const float4*)(x + (size_t)r * cD))[t];
    if (addmode == 2) {
        float4 a = ((const float4*)(add + (size_t)r * cC))[t & 15];
        v.x += a.x; v.y += a.y; v.z += a.z; v.w += a.w;
    }
    float s = warp_sum(v.x + v.y + v.z + v.w);
    if ((t & 31) == 0) wred[t >> 5] = s;
    __syncthreads();
    float mu = 0.f;
#pragma unroll
    for (int i = 0; i < 8; i++) mu += wred[i];
    mu *= (1.f / cD);
    __syncthreads();
    float dx = v.x - mu, dy = v.y - mu, dz = v.z - mu, dw = v.w - mu;
    float q = warp_sum(dx * dx + dy * dy + dz * dz + dw * dw);
    if ((t & 31) == 0) wred[t >> 5] = q;
    __syncthreads();
    float var = 0.f;
#pragma unroll
    for (int i = 0; i < 8; i++) var += wred[i];
    float inv = rsqrtf(var * (1.f / cD) + 1e-5f);
    float4 wv = ((const float4*)w)[t];
    float4 bv = ((const float4*)bias)[t];
    float4 o;
    o.x = roundtf(dx * inv * wv.x + bv.x);
    o.y = roundtf(dy * inv * wv.y + bv.y);
    o.z = roundtf(dz * inv * wv.z + bv.z);
    o.w = roundtf(dw * inv * wv.w + bv.w);
    ((float4*)(out + (size_t)r * cD))[t] = o;
}

// ---------------------------------------------------------------------------
// Fused K/V LayerNorm, register-resident.
// ---------------------------------------------------------------------------
__global__ void __launch_bounds__(256) ln2_kernel(
    const float* __restrict__ feats, const float* __restrict__ kpos,
    const float* __restrict__ kw, const float* __restrict__ kb,
    const float* __restrict__ vw, const float* __restrict__ vb,
    float* __restrict__ outk, float* __restrict__ outv) {
    __shared__ float2 wred[8];
    int r = blockIdx.x, t = threadIdx.x;
    float4 f = ((const float4*)(feats + (size_t)r * cD))[t];
    float4 kp = ((const float4*)(kpos + (size_t)r * cD))[t];
    float4 k;
    k.x = f.x + kp.x; k.y = f.y + kp.y; k.z = f.z + kp.z; k.w = f.w + kp.w;

    float sk = warp_sum(k.x + k.y + k.z + k.w);
    float sv = warp_sum(f.x + f.y + f.z + f.w);
    if ((t & 31) == 0) wred[t >> 5] = make_float2(sk, sv);
    __syncthreads();
    float muk = 0.f, muv = 0.f;
#pragma unroll
    for (int i = 0; i < 8; i++) { muk += wred[i].x; muv += wred[i].y; }
    muk *= (1.f / cD);
    muv *= (1.f / cD);
    __syncthreads();
    float kx = k.x - muk, ky = k.y - muk, kz = k.z - muk, kw4 = k.w - muk;
    float fx = f.x - muv, fy = f.y - muv, fz = f.z - muv, fw4 = f.w - muv;
    float qk = warp_sum(kx * kx + ky * ky + kz * kz + kw4 * kw4);
    float qv = warp_sum(fx * fx + fy * fy + fz * fz + fw4 * fw4);
    if ((t & 31) == 0) wred[t >> 5] = make_float2(qk, qv);
    __syncthreads();
    float vk = 0.f, vv = 0.f;
#pragma unroll
    for (int i = 0; i < 8; i++) { vk += wred[i].x; vv += wred[i].y; }
    float invk = rsqrtf(vk * (1.f / cD) + 1e-5f);
    float invv = rsqrtf(vv * (1.f / cD) + 1e-5f);

    float4 kwv = ((const float4*)kw)[t];
    float4 kbv = ((const float4*)kb)[t];
    float4 vwv = ((const float4*)vw)[t];
    float4 vbv = ((const float4*)vb)[t];
    float4 ok, ov;
    ok.x = roundtf(kx * invk * kwv.x + kbv.x);
    ok.y = roundtf(ky * invk * kwv.y + kbv.y);
    ok.z = roundtf(kz * invk * kwv.z + kbv.z);
    ok.w = roundtf(kw4 * invk * kwv.w + kbv.w);
    ov.x = roundtf(fx * invv * vwv.x + vbv.x);
    ov.y = roundtf(fy * invv * vwv.y + vbv.y);
    ov.z = roundtf(fz * invv * vwv.z + vbv.z);
    ov.w = roundtf(fw4 * invv * vwv.w + vbv.w);
    ((float4*)(outk + (size_t)r * cD))[t] = ok;
    ((float4*)(outv + (size_t)r * cD))[t] = ov;
}

// ---------------------------------------------------------------------------
// TF32 NT GEMM: 256 threads, 8 warps (2 M x 4 N), 3-stage cp.async.
// ---------------------------------------------------------------------------
template <int BM, int BN>
__global__ void __launch_bounds__(256, 2) tf32_nt(
    const float* __restrict__ A, long lda,
    const float* __restrict__ Bw, long ldb,
    float* __restrict__ Cp, long ldc,
    int K, float alpha,
    const float* __restrict__ bias, const float* __restrict__ resid,
    int do_gelu, int round_out,
    int zdiv, long a1, long a2, long b1, long b2, long c1, long c2) {
    constexpr int T = 256;
    constexpr int WTM = BM / 2;
    constexpr int WTN = BN / 4;
    constexpr int MT = WTM / 16;
    constexpr int NT = WTN / 8;
    constexpr int LDS = 36;
    constexpr int ASZ = BM * LDS;
    constexpr int BSZ = BN * LDS;
    constexpr int CA = BM * 4 / T;
    constexpr int CB = BN * 4 / T;

    extern __shared__ float smem[];
    float* As = smem;
    float* Bs = smem + 3 * ASZ;
    uint32_t as_u = smem_addr_u32(As);
    uint32_t bs_u = smem_addr_u32(Bs);

    int t = threadIdx.x, lane = t & 31, warp = t >> 5;
    int z = blockIdx.z;
    int zo = z / zdiv, zi = z - zo * zdiv;

    const float* Ab = A + zo * a1 + zi * a2 + (long)blockIdx.y * BM * lda;
    const float* Bb = Bw + zo * b1 + zi * b2 + (long)blockIdx.x * BN * ldb;

    int wm0 = (warp & 1) * WTM;
    int wn0 = (warp >> 1) * WTN;
    int nslab = K >> 4;

    float acc[MT][NT][4];
#pragma unroll
    for (int i = 0; i < MT; i++)
#pragma unroll
        for (int j = 0; j < NT; j++)
#pragma unroll
            for (int e = 0; e < 4; e++) acc[i][j][e] = 0.f;

    auto issue = [&](int s) {
        if (s < nslab) {
            long k0 = (long)s * 16;
            int st = s % 3;
#pragma unroll
            for (int i = 0; i < CA; i++) {
                int q = t + i * T;
                int row = q >> 2, c4 = (q & 3) * 4;
                CP16(as_u + (uint32_t)(st * ASZ + row * LDS + c4) * 4,
                     Ab + (long)row * lda + k0 + c4);
            }
#pragma unroll
            for (int i = 0; i < CB; i++) {
                int q = t + i * T;
                int row = q >> 2, c4 = (q & 3) * 4;
                CP16(bs_u + (uint32_t)(st * BSZ + row * LDS + c4) * 4,
                     Bb + (long)row * ldb + k0 + c4);
            }
        }
        CP_COMMIT();
    };

    issue(0); issue(1); issue(2);

    int r0 = wm0 + (lane >> 2);
    int n0 = wn0 + (lane >> 2);
    int kc0 = lane & 3;

    for (int s = 0; s < nslab; s++) {
        CP_WAIT2();
        __syncthreads();
        const float* as = As + (s % 3) * ASZ;
        const float* bs = Bs + (s % 3) * BSZ;
#pragma unroll
        for (int kq = 0; kq < 2; kq++) {
            int kc = kq * 8 + kc0;
            uint32_t af[MT][4], bf[NT][2];
#pragma unroll
            for (int i = 0; i < MT; i++) {
                int base = (r0 + i * 16) * LDS + kc;
                af[i][0] = __float_as_uint(as[base]);
                af[i][1] = __float_as_uint(as[base + 8 * LDS]);
                af[i][2] = __float_as_uint(as[base + 4]);
                af[i][3] = __float_as_uint(as[base + 8 * LDS + 4]);
            }
#pragma unroll
            for (int j = 0; j < NT; j++) {
                int base = (n0 + j * 8) * LDS + kc;
                bf[j][0] = __float_as_uint(bs[base]);
                bf[j][1] = __float_as_uint(bs[base + 4]);
            }
#pragma unroll
            for (int i = 0; i < MT; i++)
#pragma unroll
                for (int j = 0; j < NT; j++) mma8(acc[i][j], af[i], bf[j]);
        }
        __syncthreads();
        issue(s + 3);
    }

    float* Cb = Cp + zo * c1 + zi * c2;
    const float* Rb = resid ? (resid + zo * c1 + zi * c2) : (const float*)0;
    long ccol0 = (long)blockIdx.x * BN + wn0;
#pragma unroll
    for (int i = 0; i < MT; i++) {
#pragma unroll
        for (int half = 0; half < 2; half++) {
            long row = (long)blockIdx.y * BM + wm0 + i * 16 + (lane >> 2) + half * 8;
#pragma unroll
            for (int j = 0; j < NT; j++) {
                long col = ccol0 + j * 8 + 2 * (lane & 3);
                float2 o;
                o.x = acc[i][j][half * 2 + 0] * alpha;
                o.y = acc[i][j][half * 2 + 1] * alpha;
                if (bias) { o.x += bias[col]; o.y += bias[col + 1]; }
                long off = row * ldc + col;
                if (Rb) {
                    float2 rv = *(const float2*)&Rb[off];
                    o.x += rv.x; o.y += rv.y;
                }
                if (do_gelu) { o.x = gelu1(o.x); o.y = gelu1(o.y); }
                if (round_out) { o.x = roundtf(o.x); o.y = roundtf(o.y); }
                *(float2*)&Cb[off] = o;
            }
        }
    }
}

// ---------------------------------------------------------------------------
// TF32 NN GEMM: 256 threads, 8 warps (4 M x 2 N), BM=128, BN=64, 3-stage.
// ---------------------------------------------------------------------------
__global__ void __launch_bounds__(256, 2) tf32_nn(
    const float* __restrict__ A, long lda,
    const float* __restrict__ Bm, long ldb,
    float* __restrict__ Cp, long ldc,
    int K,
    const float* __restrict__ resid, int round_out,
    int ksplit, long kstride,
    int zdiv, long a1, long a2, long b1, long b2, long c1, long c2) {
    constexpr int T = 256;
    constexpr int BM = 128, BN = 64;
    constexpr int MT = 2, NT = 4;
    constexpr int LDS = 36;
    constexpr int LDB_S = BN + 8;
    constexpr int ASZ = BM * LDS;
    constexpr int BSZ = 16 * LDB_S;
    constexpr int CA = BM * 4 / T;
    constexpr int CB = 16 * BN / 4 / T;

    extern __shared__ float smemf[];
    float* As = smemf;
    float* Bs = smemf + 3 * ASZ;
    uint32_t as_u = smem_addr_u32(As);
    uint32_t bs_u = smem_addr_u32(Bs);

    int t = threadIdx.x, lane = t & 31, warp = t >> 5;
    int z = blockIdx.z;
    int kch = z % ksplit, zb = z / ksplit;
    int zo = zb / zdiv, zi = zb - zo * zdiv;
    int Kc = K / ksplit;

    const float* Ab = A + zo * a1 + zi * a2 + (long)blockIdx.y * BM * lda + (long)kch * Kc;
    const float* Bb = Bm + zo * b1 + zi * b2 + (long)blockIdx.x * BN + (long)kch * Kc * ldb;

    int wm0 = (warp & 3) * 32;
    int wn0 = (warp >> 2) * 32;
    int nslab = Kc >> 4;

    float acc[MT][NT][4];
#pragma unroll
    for (int i = 0; i < MT; i++)
#pragma unroll
        for (int j = 0; j < NT; j++)
#pragma unroll
            for (int e = 0; e < 4; e++) acc[i][j][e] = 0.f;

    auto issue = [&](int s) {
        if (s < nslab) {
            long k0 = (long)s * 16;
            int st = s % 3;
#pragma unroll
            for (int i = 0; i < CA; i++) {
                int q = t + i * T;
                int row = q >> 2, c4 = (q & 3) * 4;
                CP16(as_u + (uint32_t)(st * ASZ + row * LDS + c4) * 4,
                     Ab + (long)row * lda + k0 + c4);
            }
#pragma unroll
            for (int i = 0; i < CB; i++) {
                int q = t + i * T;
                int row = q >> 4, c4 = (q & 15) * 4;
                CP16(bs_u + (uint32_t)(st * BSZ + row * LDB_S + c4) * 4,
                     Bb + (k0 + row) * ldb + c4);
            }
        }
        CP_COMMIT();
    };

    issue(0); issue(1); issue(2);

    int r0 = wm0 + (lane >> 2);
    int nb0 = wn0 + (lane >> 2);
    int kc0 = lane & 3;

    for (int s = 0; s < nslab; s++) {
        CP_WAIT2();
        __syncthreads();
        const float* as = As + (s % 3) * ASZ;
        const float* bs = Bs + (s % 3) * BSZ;
#pragma unroll
        for (int kq = 0; kq < 2; kq++) {
            int kc = kq * 8 + kc0;
            uint32_t af[MT][4], bf[NT][2];
#pragma unroll
            for (int i = 0; i < MT; i++) {
                int base = (r0 + i * 16) * LDS + kc;
                af[i][0] = __float_as_uint(as[base]);
                af[i][1] = __float_as_uint(as[base + 8 * LDS]);
                af[i][2] = __float_as_uint(as[base + 4]);
                af[i][3] = __float_as_uint(as[base + 8 * LDS + 4]);
            }
#pragma unroll
            for (int j = 0; j < NT; j++) {
                int nn = nb0 + j * 8;
                bf[j][0] = __float_as_uint(bs[kc * LDB_S + nn]);
                bf[j][1] = __float_as_uint(bs[(kc + 4) * LDB_S + nn]);
            }
#pragma unroll
            for (int i = 0; i < MT; i++)
#pragma unroll
                for (int j = 0; j < NT; j++) mma8(acc[i][j], af[i], bf[j]);
        }
        __syncthreads();
        issue(s + 3);
    }

    float* Cb = Cp + zo * c1 + zi * c2 + (long)kch * kstride;
    const float* Rb = resid ? (resid + zo * c1 + zi * c2) : (const float*)0;
    long ccol0 = (long)blockIdx.x * BN + wn0;
#pragma unroll
    for (int i = 0; i < MT; i++) {
#pragma unroll
        for (int half = 0; half < 2; half++) {
            long row = (long)blockIdx.y * BM + wm0 + i * 16 + (lane >> 2) + half * 8;
#pragma unroll
            for (int j = 0; j < NT; j++) {
                long col = ccol0 + j * 8 + 2 * (lane & 3);
                float2 o;
                o.x = acc[i][j][half * 2 + 0];
                o.y = acc[i][j][half * 2 + 1];
                long off = row * ldc + col;
                if (Rb) {
                    float2 rv = *(const float2*)&Rb[off];
                    o.x += rv.x; o.y += rv.y;
                }
                if (round_out) { o.x = roundtf(o.x); o.y = roundtf(o.y); }
                *(float2*)&Cb[off] = o;
            }
        }
    }
}

// ---------------------------------------------------------------------------
// Split-K reduce (AV only)
// ---------------------------------------------------------------------------
__global__ void reduce_kernel(const float* __restrict__ part, long pstride,
                              float* __restrict__ out, int n) {
    int i = (blockIdx.x * 256 + threadIdx.x) * 4;
    if (i >= n) return;
    float4 v = *(const float4*)&part[i];
    float4 u = *(const float4*)&part[pstride + i];
    v.x = roundtf(v.x + u.x);
    v.y = roundtf(v.y + u.y);
    v.z = roundtf(v.z + u.z);
    v.w = roundtf(v.w + u.w);
    *(float4*)&out[i] = v;
}

// ---------------------------------------------------------------------------
// Masked softmax, vectorized, in place.
// ---------------------------------------------------------------------------
__global__ void __launch_bounds__(256) softmax_kernel(
    float* __restrict__ attn, const int* __restrict__ mask) {
    __shared__ float wred[8];
    int r = blockIdx.x;
    int t = threadIdx.x;
    int b = r / (cN * cG);
    float4* rowp = (float4*)(attn + (size_t)r * cS);
    const int4* mrow = (const int4*)(mask + b * cS);

    float4 vals[4];
    int4 msk[4];
    float mx = -INFINITY;
#pragma unroll
    for (int i = 0; i < 4; i++) {
        int idx = t + i * 256;
        vals[i] = rowp[idx];
        msk[i] = mrow[idx];
        if (!msk[i].x) mx = fmaxf(mx, vals[i].x);
        if (!msk[i].y) mx = fmaxf(mx, vals[i].y);
        if (!msk[i].z) mx = fmaxf(mx, vals[i].z);
        if (!msk[i].w) mx = fmaxf(mx, vals[i].w);
    }
    mx = warp_max(mx);
    if ((t & 31) == 0) wred[t >> 5] = mx;
    __syncthreads();
    mx = wred[0];
#pragma unroll
    for (int i = 1; i < 8; i++) mx = fmaxf(mx, wred[i]);
    __syncthreads();

    float sum = 0.f;
#pragma unroll
    for (int i = 0; i < 4; i++) {
        vals[i].x = msk[i].x ? 0.f : __expf(vals[i].x - mx);
        vals[i].y = msk[i].y ? 0.f : __expf(vals[i].y - mx);
        vals[i].z = msk[i].z ? 0.f : __expf(vals[i].z - mx);
        vals[i].w = msk[i].w ? 0.f : __expf(vals[i].w - mx);
        sum += vals[i].x + vals[i].y + vals[i].z + vals[i].w;
    }
    sum = warp_sum(sum);
    if ((t & 31) == 0) wred[t >> 5] = sum;
    __syncthreads();
    sum = 0.f;
#pragma unroll
    for (int i = 0; i < 8; i++) sum += wred[i];
    float inv = (sum > 0.f) ? 1.f / sum : 0.f;
#pragma unroll
    for (int i = 0; i < 4; i++) {
        float4 o;
        o.x = roundtf(vals[i].x * inv);
        o.y = roundtf(vals[i].y * inv);
        o.z = roundtf(vals[i].z * inv);
        o.w = roundtf(vals[i].w * inv);
        rowp[t + i * 256] = o;
    }
}

// ---------------------------------------------------------------------------
// Host launcher
// ---------------------------------------------------------------------------
extern "C" void kernel_launch(void* const* d_in, const int* in_sizes, int n_in,
                              void* d_out, int out_size) {
    const float* feats   = (const float*)d_in[0];
    const float* parts   = (const float*)d_in[1];
    const float* qpos    = (const float*)d_in[2];
    const float* kpos    = (const float*)d_in[3];
    const void*  maskraw = d_in[4];
    const float* ln_q_w  = (const float*)d_in[5];
    const float* ln_q_b  = (const float*)d_in[6];
    const float* ln_k_w  = (const float*)d_in[7];
    const float* ln_k_b  = (const float*)d_in[8];
    const float* ln_v_w  = (const float*)d_in[9];
    const float* ln_v_b  = (const float*)d_in[10];
    const float* wq      = (const float*)d_in[11];
    const float* wk      = (const float*)d_in[12];
    const float* wv      = (const float*)d_in[13];
    const float* w_proj  = (const float*)d_in[14];
    const float* b_proj  = (const float*)d_in[15];
    const float* reason_ln_w = (const float*)d_in[16];
    const float* reason_ln_b = (const float*)d_in[17];
    const float* reason_w    = (const float*)d_in[18];
    const float* mlp_ln_w    = (const float*)d_in[19];
    const float* mlp_ln_b    = (const float*)d_in[20];
    const float* fc1_w   = (const float*)d_in[21];
    const float* fc1_b   = (const float*)d_in[22];
    const float* fc2_w   = (const float*)d_in[23];
    const float* fc2_b   = (const float*)d_in[24];

    float* out_parts = (float*)d_out;
    float* out_attn  = out_parts + (size_t)cB * cN * cD;

    float *p_nk, *p_nv, *p_k, *p_v, *p_nq, *p_q, *p_ao, *p_p1, *p_p2, *p_t, *p_h, *p_part;
    float *p_cwq, *p_cwk, *p_cwv, *p_cwp, *p_cw1, *p_cw2, *p_cwr;
    int *p_mask, *p_flag;
    cudaGetSymbolAddress((void**)&p_nk, g_nk);
    cudaGetSymbolAddress((void**)&p_nv, g_nv);
    cudaGetSymbolAddress((void**)&p_k, g_k);
    cudaGetSymbolAddress((void**)&p_v, g_v);
    cudaGetSymbolAddress((void**)&p_nq, g_nq);
    cudaGetSymbolAddress((void**)&p_q, g_q);
    cudaGetSymbolAddress((void**)&p_ao, g_ao);
    cudaGetSymbolAddress((void**)&p_p1, g_p1);
    cudaGetSymbolAddress((void**)&p_p2, g_p2);
    cudaGetSymbolAddress((void**)&p_t, g_t);
    cudaGetSymbolAddress((void**)&p_h, g_h);
    cudaGetSymbolAddress((void**)&p_part, g_part);
    cudaGetSymbolAddress((void**)&p_cwq, g_cwq);
    cudaGetSymbolAddress((void**)&p_cwk, g_cwk);
    cudaGetSymbolAddress((void**)&p_cwv, g_cwv);
    cudaGetSymbolAddress((void**)&p_cwp, g_cwp);
    cudaGetSymbolAddress((void**)&p_cw1, g_cw1);
    cudaGetSymbolAddress((void**)&p_cw2, g_cw2);
    cudaGetSymbolAddress((void**)&p_cwr, g_cwr);
    cudaGetSymbolAddress((void**)&p_mask, g_mask);
    cudaGetSymbolAddress((void**)&p_flag, g_flag);

    const int SM_BIG   = 3 * (128 + 128) * 36 * 4;            // 110592
    const int SM_SMALL = 3 * (64 + 64) * 36 * 4;              // 55296
    const int SM_NN    = (3 * 128 * 36 + 3 * 16 * 72) * 4;    // 69120
    cudaFuncSetAttribute(tf32_nt<128, 128>, cudaFuncAttributeMaxDynamicSharedMemorySize, SM_BIG);
    cudaFuncSetAttribute(tf32_nt<64, 64>, cudaFuncAttributeMaxDynamicSharedMemorySize, SM_SMALL);
    cudaFuncSetAttribute(tf32_nn, cudaFuncAttributeMaxDynamicSharedMemorySize, SM_NN);

    detect_mask_kernel<<<1, 256>>>((const unsigned char*)maskraw, p_flag);
    expand_mask_kernel<<<(cB * cS + 255) / 256, 256>>>(maskraw, p_flag, p_mask);

    cvt_all_kernel<<<(cD * cD / 4 + 255) / 256, 256>>>(
        wq, wk, wv, w_proj, fc1_w, fc2_w, reason_w,
        p_cwq, p_cwk, p_cwv, p_cwp, p_cw1, p_cw2, p_cwr);

    // Q path
    ln_kernel<<<cB * cN, 256>>>(parts, qpos, 2, ln_q_w, ln_q_b, p_nq);
    tf32_nt<64, 64><<<dim3(16, 16, 1), 256, SM_SMALL>>>(
        p_nq, cD, p_cwq, cD, p_q, cD, cD, 1.f, nullptr, nullptr, 0, 1,
        1, 0, 0, 0, 0, 0, 0);

    // K/V LayerNorms fused
    ln2_kernel<<<cB * cS, 256>>>(feats, kpos, ln_k_w, ln_k_b, ln_v_w, ln_v_b, p_nk, p_nv);

    // K, V projections
    tf32_nt<128, 128><<<dim3(8, 128, 1), 256, SM_BIG>>>(
        p_nk, cD, p_cwk, cD, p_k, cD, cD, 1.f, nullptr, nullptr, 0, 1,
        1, 0, 0, 0, 0, 0, 0);
    tf32_nt<128, 128><<<dim3(8, 128, 1), 256, SM_BIG>>>(
        p_nv, cD, p_cwv, cD, p_v, cD, cD, 1.f, nullptr, nullptr, 0, 1,
        1, 0, 0, 0, 0, 0, 0);

    // Scores
    tf32_nt<128, 128><<<dim3(32, 2, cB * cG), 256, SM_BIG>>>(
        p_q, cD, p_k, cD, out_attn, (long)cG * cS, cC, 0.125f, nullptr, nullptr, 0, 0,
        cG,
        (long)cN * cD, (long)cC,
        (long)cS * cD, (long)cC,
        (long)cN * cG * cS, (long)cS);

    softmax_kernel<<<cB * cN * cG, 256>>>(out_attn, p_mask);

    // AV split-K 2 -> reduce(round)
    tf32_nn<<<dim3(1, 2, cB * cG * 2), 256, SM_NN>>>(
        out_attn, (long)cG * cS, p_v, cD, p_part, cD, cS, nullptr, 0,
        2, SMALL_MN,
        cG,
        (long)cN * cG * cS, (long)cS,
        (long)cS * cD, (long)cC,
        (long)cN * cD, (long)cC);
    reduce_kernel<<<(int)(SMALL_MN / 4 / 256), 256>>>(p_part, SMALL_MN, p_ao, (int)SMALL_MN);

    // Projection + residual
    tf32_nt<64, 64><<<dim3(16, 16, 1), 256, SM_SMALL>>>(
        p_ao, cD, p_cwp, cD, p_p1, cD, cD, 1.f, b_proj, parts, 0, 0,
        1, 0, 0, 0, 0, 0, 0);

    // Reason block
    ln_kernel<<<cB * cN, 256>>>(p_p1, nullptr, 0, reason_ln_w, reason_ln_b, p_t);
    tf32_nn<<<dim3(16, 2, cB), 256, SM_NN>>>(
        p_cwr, cN, p_t, cD, p_p2, cD, cN, p_p1, 0,
        1, 0,
        1,
        0, 0,
        (long)cN * cD, 0,
        (long)cN * cD, 0);

    // MLP
    ln_kernel<<<cB * cN, 256>>>(p_p2, nullptr, 0, mlp_ln_w, mlp_ln_b, p_t);
    tf32_nt<64, 64><<<dim3(16, 16, 1), 256, SM_SMALL>>>(
        p_t, cD, p_cw1, cD, p_h, cD, cD, 1.f, fc1_b, nullptr, 1, 1,
        1, 0, 0, 0, 0, 0, 0);
    tf32_nt<64, 64><<<dim3(16, 16, 1), 256, SM_SMALL>>>(
        p_h, cD, p_cw2, cD, out_parts, cD, cD, 1.f, fc2_b, p_p2, 0, 0,
        1, 0, 0, 0, 0, 0, 0);

    (void)in_sizes; (void)n_in; (void)out_size;
}

// round 15
// speedup vs baseline: 1.1170x; 1.1170x over previous
#include <cuda_runtime.h>
#include <math.h>
#include <stdint.h>

constexpr int cB = 4;
constexpr int cS = 4096;
constexpr int cN = 256;
constexpr int cD = 1024;
constexpr int cG = 16;
constexpr int cC = 64;
constexpr long SMALL_MN = (long)cB * cN * cD;

// ---------------------------------------------------------------------------
// Static device scratch
// ---------------------------------------------------------------------------
__device__ float g_nk [cB * cS * cD];
__device__ float g_nv [cB * cS * cD];
__device__ float g_k  [cB * cS * cD];
__device__ float g_v  [cB * cS * cD];
__device__ float g_nq [cB * cN * cD];
__device__ float g_q  [cB * cN * cD];
__device__ float g_ao [cB * cN * cD];
__device__ float g_p1 [cB * cN * cD];
__device__ float g_p2 [cB * cN * cD];
__device__ float g_t  [cB * cN * cD];
__device__ float g_h  [cB * cN * cD];
__device__ float g_part[2 * cB * cN * cD];
__device__ float g_cwq[cD * cD], g_cwk[cD * cD], g_cwv[cD * cD];
__device__ float g_cwp[cD * cD], g_cw1[cD * cD], g_cw2[cD * cD];
__device__ float g_cwr[cN * cN];
__device__ int   g_mask[cB * cS];
__device__ int   g_flag[1];

// ---------------------------------------------------------------------------
// tf32 helpers
// ---------------------------------------------------------------------------
__device__ __forceinline__ uint32_t f2tf(float f) {
    uint32_t u;
    asm("cvt.rna.tf32.f32 %0, %1;" : "=r"(u) : "f"(f));
    return u;
}
__device__ __forceinline__ float roundtf(float f) { return __uint_as_float(f2tf(f)); }

__device__ __forceinline__ void mma8(float* c, const uint32_t* a, const uint32_t* b) {
    asm volatile(
        "mma.sync.aligned.m16n8k8.row.col.f32.tf32.tf32.f32 "
        "{%0,%1,%2,%3}, {%4,%5,%6,%7}, {%8,%9}, {%0,%1,%2,%3};"
        : "+f"(c[0]), "+f"(c[1]), "+f"(c[2]), "+f"(c[3])
        : "r"(a[0]), "r"(a[1]), "r"(a[2]), "r"(a[3]), "r"(b[0]), "r"(b[1]));
}

#define CP16(smem_u32, gptr) \
    asm volatile("cp.async.ca.shared.global [%0], [%1], 16;" :: "r"(smem_u32), "l"(gptr))
#define CP_COMMIT() asm volatile("cp.async.commit_group;")
#define CP_WAIT1()  asm volatile("cp.async.wait_group 1;")

__device__ __forceinline__ uint32_t smem_addr_u32(const void* p) {
    return (uint32_t)__cvta_generic_to_shared(p);
}

__device__ __forceinline__ float gelu1(float v) {
    return 0.5f * v * (1.f + erff(v * 0.70710678118654752f));
}

__device__ __forceinline__ float warp_sum(float s) {
#pragma unroll
    for (int o = 16; o; o >>= 1) s += __shfl_xor_sync(0xffffffffu, s, o);
    return s;
}
__device__ __forceinline__ float2 warp_sum2(float2 s) {
#pragma unroll
    for (int o = 16; o; o >>= 1) {
        s.x += __shfl_xor_sync(0xffffffffu, s.x, o);
        s.y += __shfl_xor_sync(0xffffffffu, s.y, o);
    }
    return s;
}
__device__ __forceinline__ float4 warp_sum4(float4 s) {
#pragma unroll
    for (int o = 16; o; o >>= 1) {
        s.x += __shfl_xor_sync(0xffffffffu, s.x, o);
        s.y += __shfl_xor_sync(0xffffffffu, s.y, o);
        s.z += __shfl_xor_sync(0xffffffffu, s.z, o);
        s.w += __shfl_xor_sync(0xffffffffu, s.w, o);
    }
    return s;
}
__device__ __forceinline__ float warp_max(float s) {
#pragma unroll
    for (int o = 16; o; o >>= 1) s = fmaxf(s, __shfl_xor_sync(0xffffffffu, s, o));
    return s;
}

// ---------------------------------------------------------------------------
// Mask handling
// ---------------------------------------------------------------------------
__global__ void detect_mask_kernel(const unsigned char* __restrict__ p, int* flag) {
    __shared__ int red[256];
    int t = threadIdx.x;
    int cnt = 0;
    for (int i = t; i < cB * cS; i += 256)
        if ((i & 3) != 0 && p[i] != 0) cnt++;
    red[t] = cnt;
    __syncthreads();
    for (int s = 128; s > 0; s >>= 1) {
        if (t < s) red[t] += red[t + s];
        __syncthreads();
    }
    if (t == 0) flag[0] = red[0];
}

__global__ void expand_mask_kernel(const void* __restrict__ p, const int* __restrict__ flag,
                                   int* __restrict__ mout) {
    int i = blockIdx.x * 256 + threadIdx.x;
    if (i >= cB * cS) return;
    int isbyte = flag[0] > 0;
    int v = isbyte ? (int)((const unsigned char*)p)[i] : ((const int*)p)[i];
    mout[i] = (v != 0) ? 1 : 0;
}

// ---------------------------------------------------------------------------
// One-shot weight conversion, float4
// ---------------------------------------------------------------------------
__device__ __forceinline__ float4 round4(float4 v) {
    v.x = roundtf(v.x); v.y = roundtf(v.y); v.z = roundtf(v.z); v.w = roundtf(v.w);
    return v;
}

__global__ void cvt_all_kernel(
    const float* __restrict__ wq, const float* __restrict__ wk, const float* __restrict__ wv,
    const float* __restrict__ wp, const float* __restrict__ w1, const float* __restrict__ w2,
    const float* __restrict__ wr,
    float* __restrict__ dq, float* __restrict__ dk, float* __restrict__ dv,
    float* __restrict__ dp, float* __restrict__ d1, float* __restrict__ d2,
    float* __restrict__ dr) {
    int i = blockIdx.x * 256 + threadIdx.x;
    if (i < cD * cD / 4) {
        ((float4*)dq)[i] = round4(((const float4*)wq)[i]);
        ((float4*)dk)[i] = round4(((const float4*)wk)[i]);
        ((float4*)dv)[i] = round4(((const float4*)wv)[i]);
        ((float4*)dp)[i] = round4(((const float4*)wp)[i]);
        ((float4*)d1)[i] = round4(((const float4*)w1)[i]);
        ((float4*)d2)[i] = round4(((const float4*)w2)[i]);
    }
    if (i < cN * cN / 4) ((float4*)dr)[i] = round4(((const float4*)wr)[i]);
}

// ---------------------------------------------------------------------------
// LayerNorm, register-resident, SINGLE-PASS moments (var = E[x^2]-mu^2).
// ---------------------------------------------------------------------------
__global__ void __launch_bounds__(256) ln_kernel(
    const float* __restrict__ x, const float* __restrict__ add, int addmode,
    const float* __restrict__ w, const float* __restrict__ bias,
    float* __restrict__ out) {
    __shared__ float2 wred[8];
    int r = blockIdx.x, t = threadIdx.x;
    float4 v = ((const float4*)(x + (size_t)r * cD))[t];
    if (addmode == 2) {
        float4 a = ((const float4*)(add + (size_t)r * cC))[t & 15];
        v.x += a.x; v.y += a.y; v.z += a.z; v.w += a.w;
    }
    float2 m;
    m.x = v.x + v.y + v.z + v.w;
    m.y = v.x * v.x + v.y * v.y + v.z * v.z + v.w * v.w;
    m = warp_sum2(m);
    if ((t & 31) == 0) wred[t >> 5] = m;
    __syncthreads();
    float s1 = 0.f, s2 = 0.f;
#pragma unroll
    for (int i = 0; i < 8; i++) { s1 += wred[i].x; s2 += wred[i].y; }
    float mu = s1 * (1.f / cD);
    float var = s2 * (1.f / cD) - mu * mu;
    float inv = rsqrtf(var + 1e-5f);
    float4 wv = ((const float4*)w)[t];
    float4 bv = ((const float4*)bias)[t];
    float4 o;
    o.x = roundtf((v.x - mu) * inv * wv.x + bv.x);
    o.y = roundtf((v.y - mu) * inv * wv.y + bv.y);
    o.z = roundtf((v.z - mu) * inv * wv.z + bv.z);
    o.w = roundtf((v.w - mu) * inv * wv.w + bv.w);
    ((float4*)(out + (size_t)r * cD))[t] = o;
}

// ---------------------------------------------------------------------------
// Fused K/V LayerNorm, single-pass moments for both rows.
// ---------------------------------------------------------------------------
__global__ void __launch_bounds__(256) ln2_kernel(
    const float* __restrict__ feats, const float* __restrict__ kpos,
    const float* __restrict__ kw, const float* __restrict__ kb,
    const float* __restrict__ vw, const float* __restrict__ vb,
    float* __restrict__ outk, float* __restrict__ outv) {
    __shared__ float4 wred[8];
    int r = blockIdx.x, t = threadIdx.x;
    float4 f = ((const float4*)(feats + (size_t)r * cD))[t];
    float4 kp = ((const float4*)(kpos + (size_t)r * cD))[t];
    float4 k;
    k.x = f.x + kp.x; k.y = f.y + kp.y; k.z = f.z + kp.z; k.w = f.w + kp.w;

    float4 m;
    m.x = k.x + k.y + k.z + k.w;
    m.y = k.x * k.x + k.y * k.y + k.z * k.z + k.w * k.w;
    m.z = f.x + f.y + f.z + f.w;
    m.w = f.x * f.x + f.y * f.y + f.z * f.z + f.w * f.w;
    m = warp_sum4(m);
    if ((t & 31) == 0) wred[t >> 5] = m;
    __syncthreads();
    float sk1 = 0.f, sk2 = 0.f, sv1 = 0.f, sv2 = 0.f;
#pragma unroll
    for (int i = 0; i < 8; i++) {
        sk1 += wred[i].x; sk2 += wred[i].y; sv1 += wred[i].z; sv2 += wred[i].w;
    }
    float muk = sk1 * (1.f / cD);
    float vark = sk2 * (1.f / cD) - muk * muk;
    float invk = rsqrtf(vark + 1e-5f);
    float muv = sv1 * (1.f / cD);
    float varv = sv2 * (1.f / cD) - muv * muv;
    float invv = rsqrtf(varv + 1e-5f);

    float4 kwv = ((const float4*)kw)[t];
    float4 kbv = ((const float4*)kb)[t];
    float4 vwv = ((const float4*)vw)[t];
    float4 vbv = ((const float4*)vb)[t];
    float4 ok, ov;
    ok.x = roundtf((k.x - muk) * invk * kwv.x + kbv.x);
    ok.y = roundtf((k.y - muk) * invk * kwv.y + kbv.y);
    ok.z = roundtf((k.z - muk) * invk * kwv.z + kbv.z);
    ok.w = roundtf((k.w - muk) * invk * kwv.w + kbv.w);
    ov.x = roundtf((f.x - muv) * invv * vwv.x + vbv.x);
    ov.y = roundtf((f.y - muv) * invv * vwv.y + vbv.y);
    ov.z = roundtf((f.z - muv) * invv * vwv.z + vbv.z);
    ov.w = roundtf((f.w - muv) * invv * vwv.w + vbv.w);
    ((float4*)(outk + (size_t)r * cD))[t] = ok;
    ((float4*)(outv + (size_t)r * cD))[t] = ov;
}

// ---------------------------------------------------------------------------
// TF32 NT GEMM: 256 threads, 8 warps (2 M x 4 N), 2-stage cp.async.
// ---------------------------------------------------------------------------
template <int BM, int BN>
__global__ void __launch_bounds__(256, 2) tf32_nt(
    const float* __restrict__ A, long lda,
    const float* __restrict__ Bw, long ldb,
    float* __restrict__ Cp, long ldc,
    int K, float alpha,
    const float* __restrict__ bias, const float* __restrict__ resid,
    int do_gelu, int round_out,
    int zdiv, long a1, long a2, long b1, long b2, long c1, long c2) {
    constexpr int T = 256;
    constexpr int WTM = BM / 2;
    constexpr int WTN = BN / 4;
    constexpr int MT = WTM / 16;
    constexpr int NT = WTN / 8;
    constexpr int LDS = 36;
    constexpr int ASZ = BM * LDS;
    constexpr int BSZ = BN * LDS;
    constexpr int CA = BM * 4 / T;
    constexpr int CB = BN * 4 / T;

    extern __shared__ float smem[];
    float* As = smem;
    float* Bs = smem + 2 * ASZ;
    uint32_t as_u = smem_addr_u32(As);
    uint32_t bs_u = smem_addr_u32(Bs);

    int t = threadIdx.x, lane = t & 31, warp = t >> 5;
    int z = blockIdx.z;
    int zo = z / zdiv, zi = z - zo * zdiv;

    const float* Ab = A + zo * a1 + zi * a2 + (long)blockIdx.y * BM * lda;
    const float* Bb = Bw + zo * b1 + zi * b2 + (long)blockIdx.x * BN * ldb;

    int wm0 = (warp & 1) * WTM;
    int wn0 = (warp >> 1) * WTN;
    int nslab = K >> 4;

    float acc[MT][NT][4];
#pragma unroll
    for (int i = 0; i < MT; i++)
#pragma unroll
        for (int j = 0; j < NT; j++)
#pragma unroll
            for (int e = 0; e < 4; e++) acc[i][j][e] = 0.f;

    auto issue = [&](int s) {
        if (s < nslab) {
            long k0 = (long)s * 16;
            int st = s & 1;
#pragma unroll
            for (int i = 0; i < CA; i++) {
                int q = t + i * T;
                int row = q >> 2, c4 = (q & 3) * 4;
                CP16(as_u + (uint32_t)(st * ASZ + row * LDS + c4) * 4,
                     Ab + (long)row * lda + k0 + c4);
            }
#pragma unroll
            for (int i = 0; i < CB; i++) {
                int q = t + i * T;
                int row = q >> 2, c4 = (q & 3) * 4;
                CP16(bs_u + (uint32_t)(st * BSZ + row * LDS + c4) * 4,
                     Bb + (long)row * ldb + k0 + c4);
            }
        }
        CP_COMMIT();
    };

    issue(0); issue(1);

    int r0 = wm0 + (lane >> 2);
    int n0 = wn0 + (lane >> 2);
    int kc0 = lane & 3;

    for (int s = 0; s < nslab; s++) {
        CP_WAIT1();
        __syncthreads();
        const float* as = As + (s & 1) * ASZ;
        const float* bs = Bs + (s & 1) * BSZ;
#pragma unroll
        for (int kq = 0; kq < 2; kq++) {
            int kc = kq * 8 + kc0;
            uint32_t af[MT][4], bf[NT][2];
#pragma unroll
            for (int i = 0; i < MT; i++) {
                int base = (r0 + i * 16) * LDS + kc;
                af[i][0] = __float_as_uint(as[base]);
                af[i][1] = __float_as_uint(as[base + 8 * LDS]);
                af[i][2] = __float_as_uint(as[base + 4]);
                af[i][3] = __float_as_uint(as[base + 8 * LDS + 4]);
            }
#pragma unroll
            for (int j = 0; j < NT; j++) {
                int base = (n0 + j * 8) * LDS + kc;
                bf[j][0] = __float_as_uint(bs[base]);
                bf[j][1] = __float_as_uint(bs[base + 4]);
            }
#pragma unroll
            for (int i = 0; i < MT; i++)
#pragma unroll
                for (int j = 0; j < NT; j++) mma8(acc[i][j], af[i], bf[j]);
        }
        __syncthreads();
        issue(s + 2);
    }

    float* Cb = Cp + zo * c1 + zi * c2;
    const float* Rb = resid ? (resid + zo * c1 + zi * c2) : (const float*)0;
    long ccol0 = (long)blockIdx.x * BN + wn0;
#pragma unroll
    for (int i = 0; i < MT; i++) {
#pragma unroll
        for (int half = 0; half < 2; half++) {
            long row = (long)blockIdx.y * BM + wm0 + i * 16 + (lane >> 2) + half * 8;
#pragma unroll
            for (int j = 0; j < NT; j++) {
                long col = ccol0 + j * 8 + 2 * (lane & 3);
                float2 o;
                o.x = acc[i][j][half * 2 + 0] * alpha;
                o.y = acc[i][j][half * 2 + 1] * alpha;
                if (bias) { o.x += bias[col]; o.y += bias[col + 1]; }
                long off = row * ldc + col;
                if (Rb) {
                    float2 rv = *(const float2*)&Rb[off];
                    o.x += rv.x; o.y += rv.y;
                }
                if (do_gelu) { o.x = gelu1(o.x); o.y = gelu1(o.y); }
                if (round_out) { o.x = roundtf(o.x); o.y = roundtf(o.y); }
                *(float2*)&Cb[off] = o;
            }
        }
    }
}

// ---------------------------------------------------------------------------
// TF32 NN GEMM: 256 threads, 8 warps (4 M x 2 N), BM=128, BN=64, 2-stage.
// ---------------------------------------------------------------------------
__global__ void __launch_bounds__(256, 2) tf32_nn(
    const float* __restrict__ A, long lda,
    const float* __restrict__ Bm, long ldb,
    float* __restrict__ Cp, long ldc,
    int K,
    const float* __restrict__ resid, int round_out,
    int ksplit, long kstride,
    int zdiv, long a1, long a2, long b1, long b2, long c1, long c2) {
    constexpr int T = 256;
    constexpr int BM = 128, BN = 64;
    constexpr int MT = 2, NT = 4;
    constexpr int LDS = 36;
    constexpr int LDB_S = BN + 8;
    constexpr int ASZ = BM * LDS;
    constexpr int BSZ = 16 * LDB_S;
    constexpr int CA = BM * 4 / T;
    constexpr int CB = 16 * BN / 4 / T;

    extern __shared__ float smemf[];
    float* As = smemf;
    float* Bs = smemf + 2 * ASZ;
    uint32_t as_u = smem_addr_u32(As);
    uint32_t bs_u = smem_addr_u32(Bs);

    int t = threadIdx.x, lane = t & 31, warp = t >> 5;
    int z = blockIdx.z;
    int kch = z % ksplit, zb = z / ksplit;
    int zo = zb / zdiv, zi = zb - zo * zdiv;
    int Kc = K / ksplit;

    const float* Ab = A + zo * a1 + zi * a2 + (long)blockIdx.y * BM * lda + (long)kch * Kc;
    const float* Bb = Bm + zo * b1 + zi * b2 + (long)blockIdx.x * BN + (long)kch * Kc * ldb;

    int wm0 = (warp & 3) * 32;
    int wn0 = (warp >> 2) * 32;
    int nslab = Kc >> 4;

    float acc[MT][NT][4];
#pragma unroll
    for (int i = 0; i < MT; i++)
#pragma unroll
        for (int j = 0; j < NT; j++)
#pragma unroll
            for (int e = 0; e < 4; e++) acc[i][j][e] = 0.f;

    auto issue = [&](int s) {
        if (s < nslab) {
            long k0 = (long)s * 16;
            int st = s & 1;
#pragma unroll
            for (int i = 0; i < CA; i++) {
                int q = t + i * T;
                int row = q >> 2, c4 = (q & 3) * 4;
                CP16(as_u + (uint32_t)(st * ASZ + row * LDS + c4) * 4,
                     Ab + (long)row * lda + k0 + c4);
            }
#pragma unroll
            for (int i = 0; i < CB; i++) {
                int q = t + i * T;
                int row = q >> 4, c4 = (q & 15) * 4;
                CP16(bs_u + (uint32_t)(st * BSZ + row * LDB_S + c4) * 4,
                     Bb + (k0 + row) * ldb + c4);
            }
        }
        CP_COMMIT();
    };

    issue(0); issue(1);

    int r0 = wm0 + (lane >> 2);
    int nb0 = wn0 + (lane >> 2);
    int kc0 = lane & 3;

    for (int s = 0; s < nslab; s++) {
        CP_WAIT1();
        __syncthreads();
        const float* as = As + (s & 1) * ASZ;
        const float* bs = Bs + (s & 1) * BSZ;
#pragma unroll
        for (int kq = 0; kq < 2; kq++) {
            int kc = kq * 8 + kc0;
            uint32_t af[MT][4], bf[NT][2];
#pragma unroll
            for (int i = 0; i < MT; i++) {
                int base = (r0 + i * 16) * LDS + kc;
                af[i][0] = __float_as_uint(as[base]);
                af[i][1] = __float_as_uint(as[base + 8 * LDS]);
                af[i][2] = __float_as_uint(as[base + 4]);
                af[i][3] = __float_as_uint(as[base + 8 * LDS + 4]);
            }
#pragma unroll
            for (int j = 0; j < NT; j++) {
                int nn = nb0 + j * 8;
                bf[j][0] = __float_as_uint(bs[kc * LDB_S + nn]);
                bf[j][1] = __float_as_uint(bs[(kc + 4) * LDB_S + nn]);
            }
#pragma unroll
            for (int i = 0; i < MT; i++)
#pragma unroll
                for (int j = 0; j < NT; j++) mma8(acc[i][j], af[i], bf[j]);
        }
        __syncthreads();
        issue(s + 2);
    }

    float* Cb = Cp + zo * c1 + zi * c2 + (long)kch * kstride;
    const float* Rb = resid ? (resid + zo * c1 + zi * c2) : (const float*)0;
    long ccol0 = (long)blockIdx.x * BN + wn0;
#pragma unroll
    for (int i = 0; i < MT; i++) {
#pragma unroll
        for (int half = 0; half < 2; half++) {
            long row = (long)blockIdx.y * BM + wm0 + i * 16 + (lane >> 2) + half * 8;
#pragma unroll
            for (int j = 0; j < NT; j++) {
                long col = ccol0 + j * 8 + 2 * (lane & 3);
                float2 o;
                o.x = acc[i][j][half * 2 + 0];
                o.y = acc[i][j][half * 2 + 1];
                long off = row * ldc + col;
                if (Rb) {
                    float2 rv = *(const float2*)&Rb[off];
                    o.x += rv.x; o.y += rv.y;
                }
                if (round_out) { o.x = roundtf(o.x); o.y = roundtf(o.y); }
                *(float2*)&Cb[off] = o;
            }
        }
    }
}

// ---------------------------------------------------------------------------
// Split-K reduce (AV only)
// ---------------------------------------------------------------------------
__global__ void reduce_kernel(const float* __restrict__ part, long pstride,
                              float* __restrict__ out, int n) {
    int i = (blockIdx.x * 256 + threadIdx.x) * 4;
    if (i >= n) return;
    float4 v = *(const float4*)&part[i];
    float4 u = *(const float4*)&part[pstride + i];
    v.x = roundtf(v.x + u.x);
    v.y = roundtf(v.y + u.y);
    v.z = roundtf(v.z + u.z);
    v.w = roundtf(v.w + u.w);
    *(float4*)&out[i] = v;
}

// ---------------------------------------------------------------------------
// Masked softmax, vectorized, in place.
// ---------------------------------------------------------------------------
__global__ void __launch_bounds__(256) softmax_kernel(
    float* __restrict__ attn, const int* __restrict__ mask) {
    __shared__ float wred[8];
    int r = blockIdx.x;
    int t = threadIdx.x;
    int b = r / (cN * cG);
    float4* rowp = (float4*)(attn + (size_t)r * cS);
    const int4* mrow = (const int4*)(mask + b * cS);

    float4 vals[4];
    int4 msk[4];
    float mx = -INFINITY;
#pragma unroll
    for (int i = 0; i < 4; i++) {
        int idx = t + i * 256;
        vals[i] = rowp[idx];
        msk[i] = mrow[idx];
        if (!msk[i].x) mx = fmaxf(mx, vals[i].x);
        if (!msk[i].y) mx = fmaxf(mx, vals[i].y);
        if (!msk[i].z) mx = fmaxf(mx, vals[i].z);
        if (!msk[i].w) mx = fmaxf(mx, vals[i].w);
    }
    mx = warp_max(mx);
    if ((t & 31) == 0) wred[t >> 5] = mx;
    __syncthreads();
    mx = wred[0];
#pragma unroll
    for (int i = 1; i < 8; i++) mx = fmaxf(mx, wred[i]);
    __syncthreads();

    float sum = 0.f;
#pragma unroll
    for (int i = 0; i < 4; i++) {
        vals[i].x = msk[i].x ? 0.f : __expf(vals[i].x - mx);
        vals[i].y = msk[i].y ? 0.f : __expf(vals[i].y - mx);
        vals[i].z = msk[i].z ? 0.f : __expf(vals[i].z - mx);
        vals[i].w = msk[i].w ? 0.f : __expf(vals[i].w - mx);
        sum += vals[i].x + vals[i].y + vals[i].z + vals[i].w;
    }
    sum = warp_sum(sum);
    if ((t & 31) == 0) wred[t >> 5] = sum;
    __syncthreads();
    sum = 0.f;
#pragma unroll
    for (int i = 0; i < 8; i++) sum += wred[i];
    float inv = (sum > 0.f) ? 1.f / sum : 0.f;
#pragma unroll
    for (int i = 0; i < 4; i++) {
        float4 o;
        o.x = roundtf(vals[i].x * inv);
        o.y = roundtf(vals[i].y * inv);
        o.z = roundtf(vals[i].z * inv);
        o.w = roundtf(vals[i].w * inv);
        rowp[t + i * 256] = o;
    }
}

// ---------------------------------------------------------------------------
// Host launcher
// ---------------------------------------------------------------------------
extern "C" void kernel_launch(void* const* d_in, const int* in_sizes, int n_in,
                              void* d_out, int out_size) {
    const float* feats   = (const float*)d_in[0];
    const float* parts   = (const float*)d_in[1];
    const float* qpos    = (const float*)d_in[2];
    const float* kpos    = (const float*)d_in[3];
    const void*  maskraw = d_in[4];
    const float* ln_q_w  = (const float*)d_in[5];
    const float* ln_q_b  = (const float*)d_in[6];
    const float* ln_k_w  = (const float*)d_in[7];
    const float* ln_k_b  = (const float*)d_in[8];
    const float* ln_v_w  = (const float*)d_in[9];
    const float* ln_v_b  = (const float*)d_in[10];
    const float* wq      = (const float*)d_in[11];
    const float* wk      = (const float*)d_in[12];
    const float* wv      = (const float*)d_in[13];
    const float* w_proj  = (const float*)d_in[14];
    const float* b_proj  = (const float*)d_in[15];
    const float* reason_ln_w = (const float*)d_in[16];
    const float* reason_ln_b = (const float*)d_in[17];
    const float* reason_w    = (const float*)d_in[18];
    const float* mlp_ln_w    = (const float*)d_in[19];
    const float* mlp_ln_b    = (const float*)d_in[20];
    const float* fc1_w   = (const float*)d_in[21];
    const float* fc1_b   = (const float*)d_in[22];
    const float* fc2_w   = (const float*)d_in[23];
    const float* fc2_b   = (const float*)d_in[24];

    float* out_parts = (float*)d_out;
    float* out_attn  = out_parts + (size_t)cB * cN * cD;

    float *p_nk, *p_nv, *p_k, *p_v, *p_nq, *p_q, *p_ao, *p_p1, *p_p2, *p_t, *p_h, *p_part;
    float *p_cwq, *p_cwk, *p_cwv, *p_cwp, *p_cw1, *p_cw2, *p_cwr;
    int *p_mask, *p_flag;
    cudaGetSymbolAddress((void**)&p_nk, g_nk);
    cudaGetSymbolAddress((void**)&p_nv, g_nv);
    cudaGetSymbolAddress((void**)&p_k, g_k);
    cudaGetSymbolAddress((void**)&p_v, g_v);
    cudaGetSymbolAddress((void**)&p_nq, g_nq);
    cudaGetSymbolAddress((void**)&p_q, g_q);
    cudaGetSymbolAddress((void**)&p_ao, g_ao);
    cudaGetSymbolAddress((void**)&p_p1, g_p1);
    cudaGetSymbolAddress((void**)&p_p2, g_p2);
    cudaGetSymbolAddress((void**)&p_t, g_t);
    cudaGetSymbolAddress((void**)&p_h, g_h);
    cudaGetSymbolAddress((void**)&p_part, g_part);
    cudaGetSymbolAddress((void**)&p_cwq, g_cwq);
    cudaGetSymbolAddress((void**)&p_cwk, g_cwk);
    cudaGetSymbolAddress((void**)&p_cwv, g_cwv);
    cudaGetSymbolAddress((void**)&p_cwp, g_cwp);
    cudaGetSymbolAddress((void**)&p_cw1, g_cw1);
    cudaGetSymbolAddress((void**)&p_cw2, g_cw2);
    cudaGetSymbolAddress((void**)&p_cwr, g_cwr);
    cudaGetSymbolAddress((void**)&p_mask, g_mask);
    cudaGetSymbolAddress((void**)&p_flag, g_flag);

    const int SM_BIG   = 2 * (128 + 128) * 36 * 4;
    const int SM_SMALL = 2 * (64 + 64) * 36 * 4;
    const int SM_NN    = (2 * 128 * 36 + 2 * 16 * 72) * 4;
    cudaFuncSetAttribute(tf32_nt<128, 128>, cudaFuncAttributeMaxDynamicSharedMemorySize, SM_BIG);

    detect_mask_kernel<<<1, 256>>>((const unsigned char*)maskraw, p_flag);
    expand_mask_kernel<<<(cB * cS + 255) / 256, 256>>>(maskraw, p_flag, p_mask);

    cvt_all_kernel<<<(cD * cD / 4 + 255) / 256, 256>>>(
        wq, wk, wv, w_proj, fc1_w, fc2_w, reason_w,
        p_cwq, p_cwk, p_cwv, p_cwp, p_cw1, p_cw2, p_cwr);

    // Q path
    ln_kernel<<<cB * cN, 256>>>(parts, qpos, 2, ln_q_w, ln_q_b, p_nq);
    tf32_nt<64, 64><<<dim3(16, 16, 1), 256, SM_SMALL>>>(
        p_nq, cD, p_cwq, cD, p_q, cD, cD, 1.f, nullptr, nullptr, 0, 1,
        1, 0, 0, 0, 0, 0, 0);

    // K/V LayerNorms fused
    ln2_kernel<<<cB * cS, 256>>>(feats, kpos, ln_k_w, ln_k_b, ln_v_w, ln_v_b, p_nk, p_nv);

    // K, V projections
    tf32_nt<128, 128><<<dim3(8, 128, 1), 256, SM_BIG>>>(
        p_nk, cD, p_cwk, cD, p_k, cD, cD, 1.f, nullptr, nullptr, 0, 1,
        1, 0, 0, 0, 0, 0, 0);
    tf32_nt<128, 128><<<dim3(8, 128, 1), 256, SM_BIG>>>(
        p_nv, cD, p_cwv, cD, p_v, cD, cD, 1.f, nullptr, nullptr, 0, 1,
        1, 0, 0, 0, 0, 0, 0);

    // Scores
    tf32_nt<128, 128><<<dim3(32, 2, cB * cG), 256, SM_BIG>>>(
        p_q, cD, p_k, cD, out_attn, (long)cG * cS, cC, 0.125f, nullptr, nullptr, 0, 0,
        cG,
        (long)cN * cD, (long)cC,
        (long)cS * cD, (long)cC,
        (long)cN * cG * cS, (long)cS);

    softmax_kernel<<<cB * cN * cG, 256>>>(out_attn, p_mask);

    // AV split-K 2 -> reduce(round)
    tf32_nn<<<dim3(1, 2, cB * cG * 2), 256, SM_NN>>>(
        out_attn, (long)cG * cS, p_v, cD, p_part, cD, cS, nullptr, 0,
        2, SMALL_MN,
        cG,
        (long)cN * cG * cS, (long)cS,
        (long)cS * cD, (long)cC,
        (long)cN * cD, (long)cC);
    reduce_kernel<<<(int)(SMALL_MN / 4 / 256), 256>>>(p_part, SMALL_MN, p_ao, (int)SMALL_MN);

    // Projection + residual
    tf32_nt<64, 64><<<dim3(16, 16, 1), 256, SM_SMALL>>>(
        p_ao, cD, p_cwp, cD, p_p1, cD, cD, 1.f, b_proj, parts, 0, 0,
        1, 0, 0, 0, 0, 0, 0);

    // Reason block
    ln_kernel<<<cB * cN, 256>>>(p_p1, nullptr, 0, reason_ln_w, reason_ln_b, p_t);
    tf32_nn<<<dim3(16, 2, cB), 256, SM_NN>>>(
        p_cwr, cN, p_t, cD, p_p2, cD, cN, p_p1, 0,
        1, 0,
        1,
        0, 0,
        (long)cN * cD, 0,
        (long)cN * cD, 0);

    // MLP
    ln_kernel<<<cB * cN, 256>>>(p_p2, nullptr, 0, mlp_ln_w, mlp_ln_b, p_t);
    tf32_nt<64, 64><<<dim3(16, 16, 1), 256, SM_SMALL>>>(
        p_t, cD, p_cw1, cD, p_h, cD, cD, 1.f, fc1_b, nullptr, 1, 1,
        1, 0, 0, 0, 0, 0, 0);
    tf32_nt<64, 64><<<dim3(16, 16, 1), 256, SM_SMALL>>>(
        p_h, cD, p_cw2, cD, out_parts, cD, cD, 1.f, fc2_b, p_p2, 0, 0,
        1, 0, 0, 0, 0, 0, 0);

    (void)in_sizes; (void)n_in; (void)out_size;
}